// round 6
// baseline (speedup 1.0000x reference)
#include <cuda_runtime.h>
#include <math.h>

#define BB 4096
#define DD 2048
#define KK 8
#define PCOLS 25   // 3K+1

constexpr float RMIN = -5.0f;
constexpr float RMAX = 5.0f;
constexpr float MIN_BIN = 1e-3f;
constexpr float MIN_SLOPE = 1e-3f;
constexpr float MAX_SLOPE = 10.0f;

// Packed main table: [9][DD] of float4 {y_k, h, 1/w, slope_j}; row 8 = {0,0,0,slope_8}.
// dk1 for bin j is row j+1's .w — one immediate-offset LDS.32 from the float4.
__device__ float4 g_main[9 * DD];
// Interior knots x_k[1..7], SoA [7][DD].
__device__ float  g_knots[7 * DD];

__global__ void norm_kernel(const float* __restrict__ params, float* __restrict__ ld_out) {
    const int d = blockIdx.x * blockDim.x + threadIdx.x;
    if (d < DD) {
        const float* p = params + (size_t)d * PCOLS;

        float ws[KK], hs[KK], sl[KK + 1];
        float sw = 0.f, sh = 0.f;
#pragma unroll
        for (int j = 0; j < KK; j++) { float v = 1.f / (1.f + __expf(-p[j]));      ws[j] = v; sw += v; }
#pragma unroll
        for (int j = 0; j < KK; j++) { float v = 1.f / (1.f + __expf(-p[KK + j])); hs[j] = v; sh += v; }
#pragma unroll
        for (int j = 0; j < KK + 1; j++) {
            float v = 1.f / (1.f + __expf(-p[2 * KK + j]));
            sl[j] = MIN_SLOPE + v * (MAX_SLOPE - MIN_SLOPE);
        }

        const float rem = (RMAX - RMIN) - KK * MIN_BIN;
        const float fw = rem / sw;
        const float fh = rem / sh;

        float xk = RMIN, yk = RMIN;
#pragma unroll
        for (int j = 0; j < KK; j++) {
            const float wd = MIN_BIN + ws[j] * fw;
            const float ht = MIN_BIN + hs[j] * fh;
            float4 v;
            v.x = yk;
            v.y = ht;
            v.z = 1.f / wd;
            v.w = sl[j];
            g_main[j * DD + d] = v;
            xk += wd;
            yk += ht;
            if (j < 7) g_knots[j * DD + d] = xk;
        }
        g_main[8 * DD + d] = make_float4(0.f, 0.f, 0.f, sl[KK]);
    }
    const int t = blockIdx.x * blockDim.x + threadIdx.x;
    if (t < BB / 2) { ld_out[t] = 0.f; ld_out[t + BB / 2] = 0.f; }
}

#define DT 256   // columns per CTA (== blockDim.x)
#define BT 16    // rows per CTA

__global__ void __launch_bounds__(DT, 6) eval_kernel(const float* __restrict__ x,
                                                     float* __restrict__ y,
                                                     float* __restrict__ ld_out) {
    __shared__ float4 sm4[9 * DT];   // 36.9 KB -> 6 CTAs/SM fits 221/228 KB

    const int tid = threadIdx.x;
    const int lane = tid & 31;
    const int d = blockIdx.x * DT + tid;

#pragma unroll
    for (int j = 0; j < 9; j++) sm4[j * DT + tid] = g_main[j * DD + d];

    const float v1 = g_knots[0 * DD + d];
    const float v2 = g_knots[1 * DD + d];
    const float v3 = g_knots[2 * DD + d];
    const float v4 = g_knots[3 * DD + d];
    const float v5 = g_knots[4 * DD + d];
    const float v6 = g_knots[5 * DD + d];
    const float v7 = g_knots[6 * DD + d];
    __syncthreads();

    const int b0 = blockIdx.y * BT;

    // lane-dependent constants for the transpose reduction
    const bool k4 = (lane & 16) != 0;
    const bool k2 = (lane & 8)  != 0;
    const bool k1 = (lane & 4)  != 0;
    const int  red_row = ((lane >> 4) & 1) * 4 + ((lane >> 3) & 1) * 2 + ((lane >> 2) & 1);

#pragma unroll
    for (int chunk = 0; chunk < BT / 8; chunk++) {
        const float* xp = x + (size_t)(b0 + chunk * 8) * DD + d;
        float*       yp = y + (size_t)(b0 + chunk * 8) * DD + d;

        // front-batch the 8 global loads (MLP=8)
        float xin[8];
#pragma unroll
        for (int r = 0; r < 8; r++) xin[r] = __ldg(&xp[r * DD]);

        float v[8];
#pragma unroll
        for (int r = 0; r < 8; r++) {
            const float xv = xin[r];
            // clamp: spline eval at xc is exact at both edges (deriv = s0 / sK)
            const float xc = fminf(fmaxf(xv, RMIN), RMAX);

            // 3-level binary search in registers, carrying the lower knot
            int bin = 0;
            float lo = RMIN;
            if (xc >= v4) { bin = 4; lo = v4; }
            const float c2 = (bin & 4) ? v6 : v2;
            if (xc >= c2) { bin += 2; lo = c2; }
            const float c1 = (bin & 4) ? ((bin & 2) ? v7 : v5)
                                       : ((bin & 2) ? v3 : v1);
            if (xc >= c1) { bin += 1; lo = c1; }

            // one LDS.128 + one immediate-offset LDS.32 (conflict-free)
            const float4* p = &sm4[bin * DT + tid];
            const float4 t = *p;          // {y_k, h, rw, dk}
            const float dk1 = p[DT].w;    // next bin's slope

            const float s   = t.y * t.z;  // h / w
            const float xi  = (xc - lo) * t.z;
            const float xi1 = 1.f - xi;
            const float xx  = xi * xi;
            const float xx1 = xi * xi1;
            const float x11 = xi1 * xi1;

            const float num  = s * xx + t.w * xx1;
            const float den  = fmaf(dk1 + t.w - 2.f * s, xx1, s);
            const float rden = __fdividef(1.f, den);

            float yv = fmaf(t.y * num, rden, t.x);
            const float dnum = s * s * fmaf(dk1, xx, fmaf(2.f * s, xx1, t.w * x11));
            v[r] = __logf(dnum * rden * rden);

            // linear tail extension: (x - xc) is 0 in-range; slope = dk (below) / dk1 (above)
            const float tail = xv - xc;
            yv = fmaf(tail, (tail < 0.f) ? t.w : dk1, yv);

            yp[r * DD] = yv;
        }

        // Transpose-reduce 8 row-sums across the warp: 9 shuffles total.
        float w4[4];
#pragma unroll
        for (int i = 0; i < 4; i++) {
            const float keep = k4 ? v[i + 4] : v[i];
            const float send = k4 ? v[i] : v[i + 4];
            w4[i] = keep + __shfl_xor_sync(0xffffffffu, send, 16);
        }
        float w2[2];
#pragma unroll
        for (int i = 0; i < 2; i++) {
            const float keep = k2 ? w4[i + 2] : w4[i];
            const float send = k2 ? w4[i] : w4[i + 2];
            w2[i] = keep + __shfl_xor_sync(0xffffffffu, send, 8);
        }
        float z = (k1 ? w2[1] : w2[0]) + __shfl_xor_sync(0xffffffffu, k1 ? w2[0] : w2[1], 4);
        z += __shfl_xor_sync(0xffffffffu, z, 2);
        z += __shfl_xor_sync(0xffffffffu, z, 1);

        if ((lane & 3) == 0) atomicAdd(&ld_out[b0 + chunk * 8 + red_row], z);
    }
}

extern "C" void kernel_launch(void* const* d_in, const int* in_sizes, int n_in,
                              void* d_out, int out_size) {
    const float* x;
    const float* params;
    if (in_sizes[0] == BB * DD) { x = (const float*)d_in[0]; params = (const float*)d_in[1]; }
    else                        { x = (const float*)d_in[1]; params = (const float*)d_in[0]; }

    float* y_out  = (float*)d_out;              // [B, D]
    float* ld_out = y_out + (size_t)BB * DD;    // [B]

    norm_kernel<<<DD / 256, 256>>>(params, ld_out);
    dim3 grid(DD / DT, BB / BT);
    eval_kernel<<<grid, DT>>>(x, y_out, ld_out);
}

// round 7
// speedup vs baseline: 1.1493x; 1.1493x over previous
#include <cuda_runtime.h>
#include <math.h>

#define BB 4096
#define DD 2048
#define KK 8
#define PCOLS 25   // 3K+1

constexpr float RMIN = -5.0f;
constexpr float RMAX = 5.0f;
constexpr float MIN_BIN = 1e-3f;
constexpr float MIN_SLOPE = 1e-3f;
constexpr float MAX_SLOPE = 10.0f;

// Packed main table: [9][DD] of float4 {y_k, h, 1/w, slope_j}; row 8 = {0,0,0,slope_8}.
// dk1 for bin j is row j+1's .w — one immediate-offset LDS.32 from the float4.
__device__ float4 g_main[9 * DD];
// Interior knots x_k[1..7], SoA [7][DD].
__device__ float  g_knots[7 * DD];

// Warp-per-d normalization: lane j holds param j (j<25).
//  lanes 0-7:  width logits   lanes 8-15: height logits   lanes 16-24: slope logits
__global__ void __launch_bounds__(256) norm_kernel(const float* __restrict__ params,
                                                   float* __restrict__ ld_out) {
    const int lane = threadIdx.x & 31;
    const int d = (blockIdx.x * blockDim.x + threadIdx.x) >> 5;   // 0..2047

    const float* p = params + (size_t)d * PCOLS;
    const float raw = (lane < PCOLS) ? p[lane] : 0.f;
    const float sig = 1.f / (1.f + __expf(-raw));

    // sum within each 8-lane group (widths in group 0, heights in group 1)
    float gs = sig;
    gs += __shfl_xor_sync(0xffffffffu, gs, 4);
    gs += __shfl_xor_sync(0xffffffffu, gs, 2);
    gs += __shfl_xor_sync(0xffffffffu, gs, 1);

    const float rem = (RMAX - RMIN) - KK * MIN_BIN;
    const float val = MIN_BIN + sig * (rem / gs);                 // width (lanes 0-7) / height (8-15)
    const float slope = MIN_SLOPE + sig * (MAX_SLOPE - MIN_SLOPE);// lanes 16-24

    // segmented inclusive scan within 8-lane groups
    float scan = val;
    float t;
    t = __shfl_up_sync(0xffffffffu, scan, 1); if ((lane & 7) >= 1) scan += t;
    t = __shfl_up_sync(0xffffffffu, scan, 2); if ((lane & 7) >= 2) scan += t;
    t = __shfl_up_sync(0xffffffffu, scan, 4); if ((lane & 7) >= 4) scan += t;

    const int j = lane & 7;
    const float ht     = __shfl_sync(0xffffffffu, val,   8 + j);   // height_j
    const float ht_inc = __shfl_sync(0xffffffffu, scan,  8 + j);   // inclusive height sum
    const float sl_j   = __shfl_sync(0xffffffffu, slope, 16 + j);  // slope_j
    const float sl_8   = __shfl_sync(0xffffffffu, slope, 24);      // slope_K

    if (lane < 8) {
        float4 v;
        v.x = RMIN + ht_inc - ht;     // y_k (exclusive cumsum)
        v.y = ht;
        v.z = 1.f / val;              // 1/width
        v.w = sl_j;
        g_main[lane * DD + d] = v;
        if (lane < 7) g_knots[lane * DD + d] = RMIN + scan;   // x_{k+1} interior knots
    }
    if (lane == 8) g_main[8 * DD + d] = make_float4(0.f, 0.f, 0.f, sl_8);

    // zero logdet accumulator (4096 floats over 65536 threads)
    const int g = blockIdx.x * blockDim.x + threadIdx.x;
    if (g < BB) ld_out[g] = 0.f;
}

#define DT 256   // columns per CTA (== blockDim.x)
#define BT 32    // rows per CTA

__global__ void __launch_bounds__(DT) eval_kernel(const float* __restrict__ x,
                                                  float* __restrict__ y,
                                                  float* __restrict__ ld_out) {
    __shared__ float4 sm4[9 * DT];   // 36 KB

    const int tid = threadIdx.x;
    const int lane = tid & 31;
    const int d = blockIdx.x * DT + tid;

#pragma unroll
    for (int j = 0; j < 9; j++) sm4[j * DT + tid] = g_main[j * DD + d];

    const float v1 = g_knots[0 * DD + d];
    const float v2 = g_knots[1 * DD + d];
    const float v3 = g_knots[2 * DD + d];
    const float v4 = g_knots[3 * DD + d];
    const float v5 = g_knots[4 * DD + d];
    const float v6 = g_knots[5 * DD + d];
    const float v7 = g_knots[6 * DD + d];
    __syncthreads();

    const int b0 = blockIdx.y * BT;

    // lane-dependent constants for the transpose reduction
    const bool k4 = (lane & 16) != 0;
    const bool k2 = (lane & 8)  != 0;
    const bool k1 = (lane & 4)  != 0;
    const int  red_row = ((lane >> 4) & 1) * 4 + ((lane >> 3) & 1) * 2 + ((lane >> 2) & 1);

#pragma unroll
    for (int chunk = 0; chunk < BT / 8; chunk++) {
        const float* xp = x + (size_t)(b0 + chunk * 8) * DD + d;
        float*       yp = y + (size_t)(b0 + chunk * 8) * DD + d;

        // front-batch the 8 global loads (MLP=8)
        float xin[8];
#pragma unroll
        for (int r = 0; r < 8; r++) xin[r] = __ldg(&xp[r * DD]);

        float v[8];
#pragma unroll
        for (int r = 0; r < 8; r++) {
            const float xv = xin[r];
            // clamp: spline eval at xc is exact at both edges (deriv = s0 / sK)
            const float xc = fminf(fmaxf(xv, RMIN), RMAX);

            // 3-level binary search in registers, carrying the lower knot
            int bin = 0;
            float lo = RMIN;
            if (xc >= v4) { bin = 4; lo = v4; }
            const float c2 = (bin & 4) ? v6 : v2;
            if (xc >= c2) { bin += 2; lo = c2; }
            const float c1 = (bin & 4) ? ((bin & 2) ? v7 : v5)
                                       : ((bin & 2) ? v3 : v1);
            if (xc >= c1) { bin += 1; lo = c1; }

            // one LDS.128 + one immediate-offset LDS.32 (conflict-free)
            const float4* p = &sm4[bin * DT + tid];
            const float4 t = *p;          // {y_k, h, rw, dk}
            const float dk1 = p[DT].w;    // next bin's slope

            const float s   = t.y * t.z;  // h / w
            const float xi  = (xc - lo) * t.z;
            const float xi1 = 1.f - xi;
            const float xx  = xi * xi;
            const float xx1 = xi * xi1;
            const float x11 = xi1 * xi1;

            const float num  = s * xx + t.w * xx1;
            const float den  = fmaf(dk1 + t.w - 2.f * s, xx1, s);
            const float rden = __fdividef(1.f, den);

            float yv = fmaf(t.y * num, rden, t.x);
            const float dnum = s * s * fmaf(dk1, xx, fmaf(2.f * s, xx1, t.w * x11));
            v[r] = __logf(dnum * rden * rden);

            // linear tail extension: (x - xc) is 0 in-range;
            // slope select keyed on sign of xv (ready early, off the load not the clamp)
            const float tail = xv - xc;
            yv = fmaf(tail, (xv < 0.f) ? t.w : dk1, yv);

            yp[r * DD] = yv;
        }

        // Transpose-reduce 8 row-sums across the warp: 9 shuffles total.
        float w4[4];
#pragma unroll
        for (int i = 0; i < 4; i++) {
            const float keep = k4 ? v[i + 4] : v[i];
            const float send = k4 ? v[i] : v[i + 4];
            w4[i] = keep + __shfl_xor_sync(0xffffffffu, send, 16);
        }
        float w2[2];
#pragma unroll
        for (int i = 0; i < 2; i++) {
            const float keep = k2 ? w4[i + 2] : w4[i];
            const float send = k2 ? w4[i] : w4[i + 2];
            w2[i] = keep + __shfl_xor_sync(0xffffffffu, send, 8);
        }
        float z = (k1 ? w2[1] : w2[0]) + __shfl_xor_sync(0xffffffffu, k1 ? w2[0] : w2[1], 4);
        z += __shfl_xor_sync(0xffffffffu, z, 2);
        z += __shfl_xor_sync(0xffffffffu, z, 1);

        if ((lane & 3) == 0) atomicAdd(&ld_out[b0 + chunk * 8 + red_row], z);
    }
}

extern "C" void kernel_launch(void* const* d_in, const int* in_sizes, int n_in,
                              void* d_out, int out_size) {
    const float* x;
    const float* params;
    if (in_sizes[0] == BB * DD) { x = (const float*)d_in[0]; params = (const float*)d_in[1]; }
    else                        { x = (const float*)d_in[1]; params = (const float*)d_in[0]; }

    float* y_out  = (float*)d_out;              // [B, D]
    float* ld_out = y_out + (size_t)BB * DD;    // [B]

    norm_kernel<<<(DD * 32) / 256, 256>>>(params, ld_out);   // warp-per-d: 256 CTAs
    dim3 grid(DD / DT, BB / BT);
    eval_kernel<<<grid, DT>>>(x, y_out, ld_out);
}

// round 8
// speedup vs baseline: 1.2231x; 1.0643x over previous
#include <cuda_runtime.h>
#include <math.h>

#define BB 4096
#define DD 2048
#define KK 8
#define PCOLS 25   // 3K+1

constexpr float RMIN = -5.0f;
constexpr float RMAX = 5.0f;
constexpr float MIN_BIN = 1e-3f;
constexpr float MIN_SLOPE = 1e-3f;
constexpr float MAX_SLOPE = 10.0f;

// Packed main table: [9][DD] of float4 {y_k, h, 1/w, slope_j}; row 8 = {0,0,0,slope_8}.
// dk1 for bin j is row j+1's .w — one immediate-offset LDS.32 from the float4.
__device__ float4 g_main[9 * DD];
// Interior knots x_k[1..7], SoA [7][DD].
__device__ float  g_knots[7 * DD];

// Warp-per-d normalization: lane j holds param j (j<25).
__global__ void __launch_bounds__(256) norm_kernel(const float* __restrict__ params,
                                                   float* __restrict__ ld_out) {
    const int lane = threadIdx.x & 31;
    const int d = (blockIdx.x * blockDim.x + threadIdx.x) >> 5;   // 0..2047

    const float* p = params + (size_t)d * PCOLS;
    const float raw = (lane < PCOLS) ? p[lane] : 0.f;
    const float sig = 1.f / (1.f + __expf(-raw));

    // sum within each 8-lane group (widths group 0, heights group 1)
    float gs = sig;
    gs += __shfl_xor_sync(0xffffffffu, gs, 4);
    gs += __shfl_xor_sync(0xffffffffu, gs, 2);
    gs += __shfl_xor_sync(0xffffffffu, gs, 1);

    const float rem = (RMAX - RMIN) - KK * MIN_BIN;
    const float val = MIN_BIN + sig * (rem / gs);                  // width / height
    const float slope = MIN_SLOPE + sig * (MAX_SLOPE - MIN_SLOPE); // lanes 16-24

    // segmented inclusive scan within 8-lane groups
    float scan = val;
    float t;
    t = __shfl_up_sync(0xffffffffu, scan, 1); if ((lane & 7) >= 1) scan += t;
    t = __shfl_up_sync(0xffffffffu, scan, 2); if ((lane & 7) >= 2) scan += t;
    t = __shfl_up_sync(0xffffffffu, scan, 4); if ((lane & 7) >= 4) scan += t;

    const int j = lane & 7;
    const float ht     = __shfl_sync(0xffffffffu, val,   8 + j);
    const float ht_inc = __shfl_sync(0xffffffffu, scan,  8 + j);
    const float sl_j   = __shfl_sync(0xffffffffu, slope, 16 + j);
    const float sl_8   = __shfl_sync(0xffffffffu, slope, 24);

    if (lane < 8) {
        float4 v;
        v.x = RMIN + ht_inc - ht;     // y_k (exclusive cumsum)
        v.y = ht;
        v.z = 1.f / val;              // 1/width
        v.w = sl_j;
        g_main[lane * DD + d] = v;
        if (lane < 7) g_knots[lane * DD + d] = RMIN + scan;   // interior knots
    }
    if (lane == 8) g_main[8 * DD + d] = make_float4(0.f, 0.f, 0.f, sl_8);

    const int g = blockIdx.x * blockDim.x + threadIdx.x;
    if (g < BB) ld_out[g] = 0.f;
}

#define DT 256   // columns per CTA (== blockDim.x)
#define BT 32    // rows per CTA

__global__ void __launch_bounds__(DT) eval_kernel(const float* __restrict__ x,
                                                  float* __restrict__ y,
                                                  float* __restrict__ ld_out) {
    __shared__ float4 sm4[9 * DT];   // 36 KB

    const int tid = threadIdx.x;
    const int lane = tid & 31;
    const int d = blockIdx.x * DT + tid;

#pragma unroll
    for (int j = 0; j < 9; j++) sm4[j * DT + tid] = g_main[j * DD + d];

    const float v1 = g_knots[0 * DD + d];
    const float v2 = g_knots[1 * DD + d];
    const float v3 = g_knots[2 * DD + d];
    const float v4 = g_knots[3 * DD + d];
    const float v5 = g_knots[4 * DD + d];
    const float v6 = g_knots[5 * DD + d];
    const float v7 = g_knots[6 * DD + d];
    __syncthreads();

    const int b0 = blockIdx.y * BT;

    // lane-dependent constants for the transpose reduction
    const bool k4 = (lane & 16) != 0;
    const bool k2 = (lane & 8)  != 0;
    const bool k1 = (lane & 4)  != 0;
    const int  red_row = ((lane >> 4) & 1) * 4 + ((lane >> 3) & 1) * 2 + ((lane >> 2) & 1);

#pragma unroll
    for (int chunk = 0; chunk < BT / 8; chunk++) {
        const float* xp = x + (size_t)(b0 + chunk * 8) * DD + d;
        float*       yp = y + (size_t)(b0 + chunk * 8) * DD + d;

        // front-batch the 8 global loads (MLP=8)
        float xin[8];
#pragma unroll
        for (int r = 0; r < 8; r++) xin[r] = __ldg(&xp[r * DD]);

        float v[8];
#pragma unroll
        for (int r = 0; r < 8; r++) {
            const float xv = xin[r];
            // clamp: spline eval at xc is exact at both edges (deriv = s0 / sK)
            const float xc = fminf(fmaxf(xv, RMIN), RMAX);

            // 3-level binary search in registers, carrying the lower knot
            int bin = 0;
            float lo = RMIN;
            if (xc >= v4) { bin = 4; lo = v4; }
            const float c2 = (bin & 4) ? v6 : v2;
            if (xc >= c2) { bin += 2; lo = c2; }
            const float c1 = (bin & 4) ? ((bin & 2) ? v7 : v5)
                                       : ((bin & 2) ? v3 : v1);
            if (xc >= c1) { bin += 1; lo = c1; }

            // one LDS.128 + one immediate-offset LDS.32 (conflict-free)
            const float4* p = &sm4[bin * DT + tid];
            const float4 t = *p;          // {y_k, h, rw, dk}
            const float dk1 = p[DT].w;    // next bin's slope

            // Horner form with shared subexpressions:
            //   sd = s - dk,  A = dk1 + dk - 2s  (shared by den & deriv-num)
            //   num_inner = dk + sd*xi            (num = xi*num_inner)
            //   den  = s + A*xi*(1-xi)            = fma(xi, fma(A,-xi,A), s)
            //   dnum_inner = dk + 2*sd*xi + A*xi^2 (== dk1*xi^2 + 2s*xi*xi1 + dk*xi1^2)
            const float s   = t.y * t.z;          // h / w
            const float xi  = (xc - lo) * t.z;
            const float sd  = s - t.w;
            const float A   = (dk1 - s) - sd;

            const float ni  = fmaf(xi, sd, t.w);
            const float t1  = fmaf(A, -xi, A);
            const float den = fmaf(xi, t1, s);
            const float rden = __fdividef(1.f, den);

            const float di  = fmaf(fmaf(A, xi, sd + sd), xi, t.w);
            const float ss  = s * s;
            const float m   = rden * rden;
            v[r] = __logf(di * ss * m);

            float yv = fmaf(t.y * xi * ni, rden, t.x);

            // linear tail extension: (x - xc) is 0 in-range
            const float tail = xv - xc;
            yv = fmaf(tail, (xv < 0.f) ? t.w : dk1, yv);

            yp[r * DD] = yv;
        }

        // Transpose-reduce 8 row-sums across the warp: 9 shuffles total.
        float w4[4];
#pragma unroll
        for (int i = 0; i < 4; i++) {
            const float keep = k4 ? v[i + 4] : v[i];
            const float send = k4 ? v[i] : v[i + 4];
            w4[i] = keep + __shfl_xor_sync(0xffffffffu, send, 16);
        }
        float w2[2];
#pragma unroll
        for (int i = 0; i < 2; i++) {
            const float keep = k2 ? w4[i + 2] : w4[i];
            const float send = k2 ? w4[i] : w4[i + 2];
            w2[i] = keep + __shfl_xor_sync(0xffffffffu, send, 8);
        }
        float z = (k1 ? w2[1] : w2[0]) + __shfl_xor_sync(0xffffffffu, k1 ? w2[0] : w2[1], 4);
        z += __shfl_xor_sync(0xffffffffu, z, 2);
        z += __shfl_xor_sync(0xffffffffu, z, 1);

        if ((lane & 3) == 0) atomicAdd(&ld_out[b0 + chunk * 8 + red_row], z);
    }
}

extern "C" void kernel_launch(void* const* d_in, const int* in_sizes, int n_in,
                              void* d_out, int out_size) {
    const float* x;
    const float* params;
    if (in_sizes[0] == BB * DD) { x = (const float*)d_in[0]; params = (const float*)d_in[1]; }
    else                        { x = (const float*)d_in[1]; params = (const float*)d_in[0]; }

    float* y_out  = (float*)d_out;              // [B, D]
    float* ld_out = y_out + (size_t)BB * DD;    // [B]

    norm_kernel<<<(DD * 32) / 256, 256>>>(params, ld_out);   // warp-per-d
    dim3 grid(DD / DT, BB / BT);
    eval_kernel<<<grid, DT>>>(x, y_out, ld_out);
}

// round 9
// speedup vs baseline: 1.2246x; 1.0012x over previous
#include <cuda_runtime.h>
#include <math.h>

#define BB 4096
#define DD 2048
#define KK 8
#define PCOLS 25   // 3K+1

constexpr float RMIN = -5.0f;
constexpr float RMAX = 5.0f;
constexpr float MIN_BIN = 1e-3f;
constexpr float MIN_SLOPE = 1e-3f;
constexpr float MAX_SLOPE = 10.0f;

// Packed main table: [9][DD] of float4 {y_k, h, 1/w, slope_j}; row 8 = {0,0,0,slope_8}.
__device__ float4 g_main[9 * DD];
// Interior knots x_k[1..7], SoA [7][DD].
__device__ float  g_knots[7 * DD];

// Warp-per-d normalization: lane j holds param j (j<25).
__global__ void __launch_bounds__(256) norm_kernel(const float* __restrict__ params,
                                                   float* __restrict__ ld_out) {
    const int lane = threadIdx.x & 31;
    const int d = (blockIdx.x * blockDim.x + threadIdx.x) >> 5;

    const float* p = params + (size_t)d * PCOLS;
    const float raw = (lane < PCOLS) ? p[lane] : 0.f;
    const float sig = 1.f / (1.f + __expf(-raw));

    float gs = sig;
    gs += __shfl_xor_sync(0xffffffffu, gs, 4);
    gs += __shfl_xor_sync(0xffffffffu, gs, 2);
    gs += __shfl_xor_sync(0xffffffffu, gs, 1);

    const float rem = (RMAX - RMIN) - KK * MIN_BIN;
    const float val = MIN_BIN + sig * (rem / gs);
    const float slope = MIN_SLOPE + sig * (MAX_SLOPE - MIN_SLOPE);

    float scan = val;
    float t;
    t = __shfl_up_sync(0xffffffffu, scan, 1); if ((lane & 7) >= 1) scan += t;
    t = __shfl_up_sync(0xffffffffu, scan, 2); if ((lane & 7) >= 2) scan += t;
    t = __shfl_up_sync(0xffffffffu, scan, 4); if ((lane & 7) >= 4) scan += t;

    const int j = lane & 7;
    const float ht     = __shfl_sync(0xffffffffu, val,   8 + j);
    const float ht_inc = __shfl_sync(0xffffffffu, scan,  8 + j);
    const float sl_j   = __shfl_sync(0xffffffffu, slope, 16 + j);
    const float sl_8   = __shfl_sync(0xffffffffu, slope, 24);

    if (lane < 8) {
        float4 v;
        v.x = RMIN + ht_inc - ht;
        v.y = ht;
        v.z = 1.f / val;
        v.w = sl_j;
        g_main[lane * DD + d] = v;
        if (lane < 7) g_knots[lane * DD + d] = RMIN + scan;
    }
    if (lane == 8) g_main[8 * DD + d] = make_float4(0.f, 0.f, 0.f, sl_8);

    const int g = blockIdx.x * blockDim.x + threadIdx.x;
    if (g < BB) ld_out[g] = 0.f;
}

#define DT 256        // columns per CTA (== blockDim.x)
#define NCHUNK 512    // total row-chunks of 8 (BB/8)
#define GY 92         // persistent CTAs per column group (8*92=736 <= 740 capacity)

__global__ void __launch_bounds__(DT) eval_kernel(const float* __restrict__ x,
                                                  float* __restrict__ y,
                                                  float* __restrict__ ld_out) {
    __shared__ float4 sm4[9 * DT];   // 36 KB

    const int tid = threadIdx.x;
    const int lane = tid & 31;
    const int d = blockIdx.x * DT + tid;

#pragma unroll
    for (int j = 0; j < 9; j++) sm4[j * DT + tid] = g_main[j * DD + d];

    const float v1 = g_knots[0 * DD + d];
    const float v2 = g_knots[1 * DD + d];
    const float v3 = g_knots[2 * DD + d];
    const float v4 = g_knots[3 * DD + d];
    const float v5 = g_knots[4 * DD + d];
    const float v6 = g_knots[5 * DD + d];
    const float v7 = g_knots[6 * DD + d];
    __syncthreads();

    // lane-dependent constants for the transpose reduction
    const bool k4 = (lane & 16) != 0;
    const bool k2 = (lane & 8)  != 0;
    const bool k1 = (lane & 4)  != 0;
    const int  red_row = ((lane >> 4) & 1) * 4 + ((lane >> 3) & 1) * 2 + ((lane >> 2) & 1);

    // persistent grid-stride over row-chunks: single wave, no quantization tail
    for (int c = blockIdx.y; c < NCHUNK; c += GY) {
        const int b0 = c * 8;
        const float* xp = x + (size_t)b0 * DD + d;
        float*       yp = y + (size_t)b0 * DD + d;

        // front-batch the 8 global loads (MLP=8)
        float xin[8];
#pragma unroll
        for (int r = 0; r < 8; r++) xin[r] = __ldg(&xp[r * DD]);

        float v[8];
#pragma unroll
        for (int r = 0; r < 8; r++) {
            const float xv = xin[r];
            // clamp: spline eval at xc is exact at both edges (deriv = s0 / sK)
            const float xc = fminf(fmaxf(xv, RMIN), RMAX);

            // 3-level binary search in registers, carrying the lower knot
            int bin = 0;
            float lo = RMIN;
            if (xc >= v4) { bin = 4; lo = v4; }
            const float c2 = (bin & 4) ? v6 : v2;
            if (xc >= c2) { bin += 2; lo = c2; }
            const float c1 = (bin & 4) ? ((bin & 2) ? v7 : v5)
                                       : ((bin & 2) ? v3 : v1);
            if (xc >= c1) { bin += 1; lo = c1; }

            // one LDS.128 + one immediate-offset LDS.32 (conflict-free)
            const float4* p = &sm4[bin * DT + tid];
            const float4 t = *p;          // {y_k, h, rw, dk}
            const float dk1 = p[DT].w;    // next bin's slope

            // Horner form with shared subexpressions
            const float s   = t.y * t.z;          // h / w
            const float xi  = (xc - lo) * t.z;
            const float sd  = s - t.w;
            const float A   = (dk1 - s) - sd;

            const float ni  = fmaf(xi, sd, t.w);
            const float t1  = fmaf(A, -xi, A);
            const float den = fmaf(xi, t1, s);
            const float rden = __fdividef(1.f, den);

            const float di  = fmaf(fmaf(A, xi, sd + sd), xi, t.w);
            const float ss  = s * s;
            const float m   = rden * rden;
            v[r] = __logf(di * ss * m);

            float yv = fmaf(t.y * xi * ni, rden, t.x);

            // linear tail extension: (x - xc) is 0 in-range
            const float tail = xv - xc;
            yv = fmaf(tail, (xv < 0.f) ? t.w : dk1, yv);

            yp[r * DD] = yv;
        }

        // Transpose-reduce 8 row-sums across the warp: 9 shuffles total.
        float w4[4];
#pragma unroll
        for (int i = 0; i < 4; i++) {
            const float keep = k4 ? v[i + 4] : v[i];
            const float send = k4 ? v[i] : v[i + 4];
            w4[i] = keep + __shfl_xor_sync(0xffffffffu, send, 16);
        }
        float w2[2];
#pragma unroll
        for (int i = 0; i < 2; i++) {
            const float keep = k2 ? w4[i + 2] : w4[i];
            const float send = k2 ? w4[i] : w4[i + 2];
            w2[i] = keep + __shfl_xor_sync(0xffffffffu, send, 8);
        }
        float z = (k1 ? w2[1] : w2[0]) + __shfl_xor_sync(0xffffffffu, k1 ? w2[0] : w2[1], 4);
        z += __shfl_xor_sync(0xffffffffu, z, 2);
        z += __shfl_xor_sync(0xffffffffu, z, 1);

        if ((lane & 3) == 0) atomicAdd(&ld_out[b0 + red_row], z);
    }
}

extern "C" void kernel_launch(void* const* d_in, const int* in_sizes, int n_in,
                              void* d_out, int out_size) {
    const float* x;
    const float* params;
    if (in_sizes[0] == BB * DD) { x = (const float*)d_in[0]; params = (const float*)d_in[1]; }
    else                        { x = (const float*)d_in[1]; params = (const float*)d_in[0]; }

    float* y_out  = (float*)d_out;              // [B, D]
    float* ld_out = y_out + (size_t)BB * DD;    // [B]

    norm_kernel<<<(DD * 32) / 256, 256>>>(params, ld_out);   // warp-per-d
    dim3 grid(DD / DT, GY);
    eval_kernel<<<grid, DT>>>(x, y_out, ld_out);
}